// round 6
// baseline (speedup 1.0000x reference)
#include <cuda_runtime.h>
#include <math.h>

#define HID   1024
#define BSZ   16
#define NOPT  4
#define ROWS  (BSZ*NOPT)    // 64
#define TRUN  2
#define SEQ   1536
#define PLEN  512
#define QLEN  128

#define KSPLIT 32
#define KCHUNK (HID/KSPLIT)   // 32
#define NTILE  64
#define NBG    (16*KSPLIT)    // 512 gemm CTAs

// Scratch (device globals — no allocation allowed)
__device__ float g_feats[ROWS*HID];
__device__ float g_h1[ROWS*HID];
__device__ float g_h2[ROWS*HID];
__device__ float g_logits[ROWS];

// Tail-fence counters (reset by prep_kernel each call -> graph-replay safe)
__device__ unsigned g_done1;
__device__ unsigned g_done2;

// ---------------------------------------------------------------------------
// f32x2 helpers (Blackwell packed fp32 pipe; PTX-only)
// ---------------------------------------------------------------------------
__device__ __forceinline__ unsigned long long bcast_f32x2(float v) {
    unsigned long long r;
    asm("mov.b64 %0, {%1, %1};" : "=l"(r) : "r"(__float_as_uint(v)));
    return r;
}
__device__ __forceinline__ void fma_f32x2(unsigned long long& acc,
                                          unsigned long long a,
                                          unsigned long long b) {
    asm("fma.rn.f32x2 %0, %1, %2, %0;" : "+l"(acc) : "l"(a), "l"(b));
}
__device__ __forceinline__ float lo_f(unsigned long long v) {
    return __uint_as_float((unsigned)(v & 0xFFFFFFFFull));
}
__device__ __forceinline__ float hi_f(unsigned long long v) {
    return __uint_as_float((unsigned)(v >> 32));
}

__device__ __forceinline__ long long opt_at(const void* p, bool is64, int i) {
    if (is64) return ((const long long*)p)[i];
    return (long long)((const int*)p)[i];
}

// ---------------------------------------------------------------------------
// 1) prep: 64 CTAs. CTA r: h1[r]=b1, h2[r]=b2, feats[r]=gather. Resets counters.
// ---------------------------------------------------------------------------
__global__ void __launch_bounds__(256)
prep_kernel(const float* __restrict__ emb, const void* __restrict__ opt_length,
            const float* __restrict__ b1, const float* __restrict__ b2) {
    const int row = blockIdx.x;
    const int tid = threadIdx.x;
    if (row == 0 && tid == 0) { g_done1 = 0; g_done2 = 0; }

    const int h4 = tid * 4;
    *(float4*)(g_h1 + (size_t)row * HID + h4) = *(const float4*)(b1 + h4);
    *(float4*)(g_h2 + (size_t)row * HID + h4) = *(const float4*)(b2 + h4);

    const int b = row >> 2, o = row & 3;
    bool is64 = (((const int*)opt_length)[1] == 0);
    long long cs = 0;
    for (int i = 0; i <= o; i++) cs += opt_at(opt_length, is64, i);
    int ohead = PLEN + QLEN + (int)cs;
    int otail = ohead + (int)opt_at(opt_length, is64, o + 1) - 1;
    int pos[6] = {0, PLEN - 1, PLEN, PLEN + QLEN - 1, ohead, otail};

    float4 acc = make_float4(0.f, 0.f, 0.f, 0.f);
    #pragma unroll
    for (int t = 0; t < TRUN; t++) {
        const float* base = emb + (size_t)(t * BSZ + b) * SEQ * HID;
        #pragma unroll
        for (int p = 0; p < 6; p++) {
            float4 v = *(const float4*)(base + (size_t)pos[p] * HID + h4);
            acc.x += v.x; acc.y += v.y; acc.z += v.z; acc.w += v.w;
        }
    }
    const float s = 0.25f;
    *(float4*)(g_feats + (size_t)row * HID + h4) =
        make_float4(acc.x * s, acc.y * s, acc.z * s, acc.w * s);
}

// ---------------------------------------------------------------------------
// 2) Split-K GEMM (as R4, which measured well): out += A(64xK) @ W(KxN),
//    64x64 tile, K-chunk 32, grid (16,32)=512 CTAs, 4x4 micro via FFMA2,
//    red.global.add.v4 epilogue onto bias-initialized out.
//    LAYER==1 additionally runs the fused tail: ticket fence -> gemv -> loss.
// ---------------------------------------------------------------------------
template <int LAYER>
__global__ void __launch_bounds__(256)
gemm_kernel(const float* __restrict__ W, const float* __restrict__ W3,
            const int* __restrict__ y, float* __restrict__ out, int out_size) {
    __shared__ float As[KCHUNK][68];   // [k][row]
    __shared__ float Ws[KCHUNK][64];   // [k][col]
    __shared__ unsigned s_ticket;
    __shared__ float red[8];

    const float* A  = (LAYER == 0) ? g_feats : g_h1;
    float*      dst = (LAYER == 0) ? g_h1    : g_h2;

    const int cta = blockIdx.y * gridDim.x + blockIdx.x;
    const int n0  = blockIdx.x * NTILE;
    const int k0  = blockIdx.y * KCHUNK;
    const int tid = threadIdx.x;

    // Load A tile 64 rows x 32 k, float4 over k, store transposed [k][row].
    {
        int kk4 = (tid & 7) * 4;
        int r   = tid >> 3;
        #pragma unroll
        for (int rr = 0; rr < 2; rr++) {
            int row = r + rr * 32;
            float4 v = *(const float4*)(A + (size_t)row * HID + k0 + kk4);
            if (LAYER == 1) {
                v.x = fmaxf(v.x, 0.f); v.y = fmaxf(v.y, 0.f);
                v.z = fmaxf(v.z, 0.f); v.w = fmaxf(v.w, 0.f);
            }
            As[kk4 + 0][row] = v.x;
            As[kk4 + 1][row] = v.y;
            As[kk4 + 2][row] = v.z;
            As[kk4 + 3][row] = v.w;
        }
    }
    // Load W tile 32 k x 64 n, float4 over n.
    {
        int c4 = (tid & 15) * 4;
        int kk = tid >> 4;
        #pragma unroll
        for (int i = 0; i < 2; i++) {
            int k = kk + i * 16;
            *(float4*)&Ws[k][c4] =
                *(const float4*)(W + (size_t)(k0 + k) * HID + n0 + c4);
        }
    }
    __syncthreads();

    const int c0 = (tid & 15) * 4;
    const int r0 = (tid >> 4) * 4;

    unsigned long long accP[4][2] = {};
    #pragma unroll
    for (int kk = 0; kk < KCHUNK; kk++) {
        ulonglong2 ap = *(const ulonglong2*)&As[kk][r0];
        float4 w = *(const float4*)&Ws[kk][c0];
        unsigned long long w0 = bcast_f32x2(w.x);
        unsigned long long w1 = bcast_f32x2(w.y);
        unsigned long long w2 = bcast_f32x2(w.z);
        unsigned long long w3 = bcast_f32x2(w.w);
        fma_f32x2(accP[0][0], ap.x, w0); fma_f32x2(accP[0][1], ap.y, w0);
        fma_f32x2(accP[1][0], ap.x, w1); fma_f32x2(accP[1][1], ap.y, w1);
        fma_f32x2(accP[2][0], ap.x, w2); fma_f32x2(accP[2][1], ap.y, w2);
        fma_f32x2(accP[3][0], ap.x, w3); fma_f32x2(accP[3][1], ap.y, w3);
    }

    #pragma unroll
    for (int i = 0; i < 4; i++) {
        int h = i >> 1;
        float v0 = (i & 1) ? hi_f(accP[0][h]) : lo_f(accP[0][h]);
        float v1 = (i & 1) ? hi_f(accP[1][h]) : lo_f(accP[1][h]);
        float v2 = (i & 1) ? hi_f(accP[2][h]) : lo_f(accP[2][h]);
        float v3 = (i & 1) ? hi_f(accP[3][h]) : lo_f(accP[3][h]);
        float* p = dst + (size_t)(r0 + i) * HID + n0 + c0;
        asm volatile("red.global.add.v4.f32 [%0], {%1, %2, %3, %4};"
                     :: "l"(p), "f"(v0), "f"(v1), "f"(v2), "f"(v3) : "memory");
    }

    if (LAYER == 1) {
        // ---- one-way fence-and-count tail: gemv + loss ----
        __threadfence();                     // release this thread's REDGs
        __syncthreads();
        if (tid == 0) s_ticket = atomicAdd(&g_done1, 1u);
        __syncthreads();
        unsigned ticket = s_ticket;
        if (ticket < NBG - ROWS) return;     // 448 CTAs exit immediately

        int row = (int)ticket - (NBG - ROWS);   // deterministic row 0..63
        if (tid == 0) {
            while (*(volatile unsigned*)&g_done1 < (unsigned)NBG) __nanosleep(32);
            __threadfence();                 // acquire: all REDGs visible
        }
        __syncthreads();

        const float* hrow = g_h2 + (size_t)row * HID;
        float4 hv = __ldcg((const float4*)(hrow + tid * 4));
        float4 wv = *(const float4*)(W3 + tid * 4);
        float s = fmaxf(hv.x, 0.f) * wv.x + fmaxf(hv.y, 0.f) * wv.y
                + fmaxf(hv.z, 0.f) * wv.z + fmaxf(hv.w, 0.f) * wv.w;
        #pragma unroll
        for (int off = 16; off; off >>= 1)
            s += __shfl_down_sync(0xFFFFFFFFu, s, off);
        if ((tid & 31) == 0) red[tid >> 5] = s;
        __syncthreads();

        if (tid == 0) {
            float logit = 0.f;
            #pragma unroll
            for (int i = 0; i < 8; i++) logit += red[i];
            g_logits[row] = logit;
            if (out_size >= ROWS) out[row] = logit;
            __threadfence();                 // release logit
            unsigned t2 = atomicAdd(&g_done2, 1u);
            if (t2 == ROWS - 1) {            // last gemv finisher computes loss
                __threadfence();             // acquire all logits
                float loss = 0.f;
                #pragma unroll
                for (int b = 0; b < BSZ; b++) {
                    float l0 = __ldcg(&g_logits[b * NOPT + 0]);
                    float l1 = __ldcg(&g_logits[b * NOPT + 1]);
                    float l2 = __ldcg(&g_logits[b * NOPT + 2]);
                    float l3 = __ldcg(&g_logits[b * NOPT + 3]);
                    float m = fmaxf(fmaxf(l0, l1), fmaxf(l2, l3));
                    float se = expf(l0 - m) + expf(l1 - m)
                             + expf(l2 - m) + expf(l3 - m);
                    float lse = m + logf(se);
                    int yy = y[b];
                    float ly = (yy == 0) ? l0 : (yy == 1) ? l1 : (yy == 2) ? l2 : l3;
                    loss -= (ly - lse);
                }
                loss /= (float)BSZ;
                if (out_size == 1)             out[0] = loss;
                else if (out_size >= ROWS + 1) out[ROWS] = loss;
            }
        }
    }
}

// ---------------------------------------------------------------------------
// Launch — 3 kernels
// inputs: 0=embeddings 1=W1 2=b1 3=W2 4=b2 5=W3 6=y 7=opt_length
// ---------------------------------------------------------------------------
extern "C" void kernel_launch(void* const* d_in, const int* in_sizes, int n_in,
                              void* d_out, int out_size) {
    const float* emb = (const float*)d_in[0];
    const float* W1  = (const float*)d_in[1];
    const float* b1  = (const float*)d_in[2];
    const float* W2  = (const float*)d_in[3];
    const float* b2  = (const float*)d_in[4];
    const float* W3  = (const float*)d_in[5];
    const int*   y   = (const int*)d_in[6];
    const void*  opt = (const void*)d_in[7];
    float* out = (float*)d_out;

    prep_kernel<<<ROWS, 256>>>(emb, opt, b1, b2);
    gemm_kernel<0><<<dim3(16, KSPLIT), 256>>>(W1, nullptr, nullptr, nullptr, 0);
    gemm_kernel<1><<<dim3(16, KSPLIT), 256>>>(W2, W3, y, out, out_size);
}

// round 7
// speedup vs baseline: 1.0906x; 1.0906x over previous
#include <cuda_runtime.h>
#include <math.h>

#define HID   1024
#define BSZ   16
#define NOPT  4
#define ROWS  (BSZ*NOPT)    // 64
#define TRUN  2
#define SEQ   1536
#define PLEN  512
#define QLEN  128

#define KSPLIT 32
#define KCHUNK (HID/KSPLIT)   // 32
#define NTILE  64

// Scratch (device globals — no allocation allowed)
__device__ float g_feats[ROWS*HID];
__device__ float g_h1[ROWS*HID];
__device__ float g_h2[ROWS*HID];
__device__ float g_logits[ROWS];
__device__ unsigned g_done;    // 64-wide gemv completion counter

// ---------------------------------------------------------------------------
// f32x2 helpers (Blackwell packed fp32 pipe; PTX-only)
// ---------------------------------------------------------------------------
__device__ __forceinline__ unsigned long long bcast_f32x2(float v) {
    unsigned long long r;
    asm("mov.b64 %0, {%1, %1};" : "=l"(r) : "r"(__float_as_uint(v)));
    return r;
}
__device__ __forceinline__ void fma_f32x2(unsigned long long& acc,
                                          unsigned long long a,
                                          unsigned long long b) {
    asm("fma.rn.f32x2 %0, %1, %2, %0;" : "+l"(acc) : "l"(a), "l"(b));
}
__device__ __forceinline__ float lo_f(unsigned long long v) {
    return __uint_as_float((unsigned)(v & 0xFFFFFFFFull));
}
__device__ __forceinline__ float hi_f(unsigned long long v) {
    return __uint_as_float((unsigned)(v >> 32));
}

__device__ __forceinline__ long long opt_at(const void* p, bool is64, int i) {
    if (is64) return ((const long long*)p)[i];
    return (long long)((const int*)p)[i];
}

// ---------------------------------------------------------------------------
// 1) prep (R4 layout, 320 CTAs): blocks [0,256) bias-init h1/h2;
//    blocks [256,320) compute feats rows. Also resets g_done.
// ---------------------------------------------------------------------------
__global__ void __launch_bounds__(256)
prep_kernel(const float* __restrict__ emb, const void* __restrict__ opt_length,
            const float* __restrict__ b1, const float* __restrict__ b2) {
    if (blockIdx.x == 0 && threadIdx.x == 0) g_done = 0;

    if (blockIdx.x < 256) {
        int i = blockIdx.x * 256 + threadIdx.x;     // 0..65535
        int j = i & (HID - 1);
        g_h1[i] = b1[j];
        g_h2[i] = b2[j];
        return;
    }
    int row = blockIdx.x - 256;      // b*NOPT + o
    int b = row >> 2, o = row & 3;

    bool is64 = (((const int*)opt_length)[1] == 0);
    long long cs = 0;
    for (int i = 0; i <= o; i++) cs += opt_at(opt_length, is64, i);
    int ohead = PLEN + QLEN + (int)cs;
    int otail = ohead + (int)opt_at(opt_length, is64, o + 1) - 1;
    int pos[6] = {0, PLEN - 1, PLEN, PLEN + QLEN - 1, ohead, otail};

    int h4 = threadIdx.x * 4;
    float4 acc = make_float4(0.f, 0.f, 0.f, 0.f);
    #pragma unroll
    for (int t = 0; t < TRUN; t++) {
        const float* base = emb + (size_t)(t * BSZ + b) * SEQ * HID;
        #pragma unroll
        for (int p = 0; p < 6; p++) {
            float4 v = *(const float4*)(base + (size_t)pos[p] * HID + h4);
            acc.x += v.x; acc.y += v.y; acc.z += v.z; acc.w += v.w;
        }
    }
    const float s = 0.25f;
    *(float4*)(g_feats + (size_t)row * HID + h4) =
        make_float4(acc.x * s, acc.y * s, acc.z * s, acc.w * s);
}

// ---------------------------------------------------------------------------
// 2) Split-K GEMM (exact R4 version — measured good): out += A(64xK)@W(KxN),
//    64x64 tile, K-chunk 32, grid (16,32)=512 CTAs, 4x4 micro via FFMA2,
//    red.global.add.v4 epilogue onto bias-initialized out.
// ---------------------------------------------------------------------------
template <int LAYER>
__global__ void __launch_bounds__(256, 6)
gemm_kernel(const float* __restrict__ W) {
    __shared__ float As[KCHUNK][68];   // [k][row], pitch 68
    __shared__ float Ws[KCHUNK][64];   // [k][col]

    const float* A  = (LAYER == 0) ? g_feats : g_h1;
    float*      out = (LAYER == 0) ? g_h1    : g_h2;

    const int n0  = blockIdx.x * NTILE;
    const int k0  = blockIdx.y * KCHUNK;
    const int tid = threadIdx.x;

    {
        int kk4 = (tid & 7) * 4;
        int r   = tid >> 3;
        #pragma unroll
        for (int rr = 0; rr < 2; rr++) {
            int row = r + rr * 32;
            float4 v = *(const float4*)(A + (size_t)row * HID + k0 + kk4);
            if (LAYER == 1) {
                v.x = fmaxf(v.x, 0.f); v.y = fmaxf(v.y, 0.f);
                v.z = fmaxf(v.z, 0.f); v.w = fmaxf(v.w, 0.f);
            }
            As[kk4 + 0][row] = v.x;
            As[kk4 + 1][row] = v.y;
            As[kk4 + 2][row] = v.z;
            As[kk4 + 3][row] = v.w;
        }
    }
    {
        int c4 = (tid & 15) * 4;
        int kk = tid >> 4;
        #pragma unroll
        for (int i = 0; i < 2; i++) {
            int k = kk + i * 16;
            *(float4*)&Ws[k][c4] =
                *(const float4*)(W + (size_t)(k0 + k) * HID + n0 + c4);
        }
    }
    __syncthreads();

    const int c0 = (tid & 15) * 4;
    const int r0 = (tid >> 4) * 4;

    unsigned long long accP[4][2] = {};
    #pragma unroll
    for (int kk = 0; kk < KCHUNK; kk++) {
        ulonglong2 ap = *(const ulonglong2*)&As[kk][r0];
        float4 w = *(const float4*)&Ws[kk][c0];
        unsigned long long w0 = bcast_f32x2(w.x);
        unsigned long long w1 = bcast_f32x2(w.y);
        unsigned long long w2 = bcast_f32x2(w.z);
        unsigned long long w3 = bcast_f32x2(w.w);
        fma_f32x2(accP[0][0], ap.x, w0); fma_f32x2(accP[0][1], ap.y, w0);
        fma_f32x2(accP[1][0], ap.x, w1); fma_f32x2(accP[1][1], ap.y, w1);
        fma_f32x2(accP[2][0], ap.x, w2); fma_f32x2(accP[2][1], ap.y, w2);
        fma_f32x2(accP[3][0], ap.x, w3); fma_f32x2(accP[3][1], ap.y, w3);
    }

    #pragma unroll
    for (int i = 0; i < 4; i++) {
        int h = i >> 1;
        float v0 = (i & 1) ? hi_f(accP[0][h]) : lo_f(accP[0][h]);
        float v1 = (i & 1) ? hi_f(accP[1][h]) : lo_f(accP[1][h]);
        float v2 = (i & 1) ? hi_f(accP[2][h]) : lo_f(accP[2][h]);
        float v3 = (i & 1) ? hi_f(accP[3][h]) : lo_f(accP[3][h]);
        float* p = out + (size_t)(r0 + i) * HID + n0 + c0;
        asm volatile("red.global.add.v4.f32 [%0], {%1, %2, %3, %4};"
                     :: "l"(p), "f"(v0), "f"(v1), "f"(v2), "f"(v3) : "memory");
    }
}

// ---------------------------------------------------------------------------
// 3) fused gemv + loss: 64 CTAs, one row each; 64-wide done-counter,
//    last finisher computes softmax loss. Counter reset by prep (graph order).
// ---------------------------------------------------------------------------
__global__ void __launch_bounds__(256)
gemv_loss_kernel(const float* __restrict__ W3, const int* __restrict__ y,
                 float* __restrict__ out, int out_size) {
    __shared__ float red[8];
    const int row = blockIdx.x;
    const int tid = threadIdx.x;

    const float* h = g_h2 + (size_t)row * HID;
    float4 hv = *(const float4*)(h + tid * 4);
    float4 wv = *(const float4*)(W3 + tid * 4);
    float s = fmaxf(hv.x, 0.f) * wv.x + fmaxf(hv.y, 0.f) * wv.y
            + fmaxf(hv.z, 0.f) * wv.z + fmaxf(hv.w, 0.f) * wv.w;
    #pragma unroll
    for (int off = 16; off; off >>= 1)
        s += __shfl_down_sync(0xFFFFFFFFu, s, off);
    if ((tid & 31) == 0) red[tid >> 5] = s;
    __syncthreads();

    if (tid == 0) {
        float logit = 0.f;
        #pragma unroll
        for (int i = 0; i < 8; i++) logit += red[i];
        g_logits[row] = logit;
        if (out_size >= ROWS) out[row] = logit;

        __threadfence();                    // release logit
        unsigned t = atomicAdd(&g_done, 1u);
        if (t == ROWS - 1) {                // last finisher: loss
            __threadfence();                // acquire all logits
            float loss = 0.f;
            #pragma unroll
            for (int b = 0; b < BSZ; b++) {
                float l0 = __ldcg(&g_logits[b * NOPT + 0]);
                float l1 = __ldcg(&g_logits[b * NOPT + 1]);
                float l2 = __ldcg(&g_logits[b * NOPT + 2]);
                float l3 = __ldcg(&g_logits[b * NOPT + 3]);
                float m = fmaxf(fmaxf(l0, l1), fmaxf(l2, l3));
                float se = expf(l0 - m) + expf(l1 - m)
                         + expf(l2 - m) + expf(l3 - m);
                float lse = m + logf(se);
                int yy = y[b];
                float ly = (yy == 0) ? l0 : (yy == 1) ? l1 : (yy == 2) ? l2 : l3;
                loss -= (ly - lse);
            }
            loss /= (float)BSZ;
            if (out_size == 1)             out[0] = loss;
            else if (out_size >= ROWS + 1) out[ROWS] = loss;
        }
    }
}

// ---------------------------------------------------------------------------
// Launch — 4 kernels
// inputs: 0=embeddings 1=W1 2=b1 3=W2 4=b2 5=W3 6=y 7=opt_length
// ---------------------------------------------------------------------------
extern "C" void kernel_launch(void* const* d_in, const int* in_sizes, int n_in,
                              void* d_out, int out_size) {
    const float* emb = (const float*)d_in[0];
    const float* W1  = (const float*)d_in[1];
    const float* b1  = (const float*)d_in[2];
    const float* W2  = (const float*)d_in[3];
    const float* b2  = (const float*)d_in[4];
    const float* W3  = (const float*)d_in[5];
    const int*   y   = (const int*)d_in[6];
    const void*  opt = (const void*)d_in[7];
    float* out = (float*)d_out;

    prep_kernel<<<320, 256>>>(emb, opt, b1, b2);
    gemm_kernel<0><<<dim3(16, KSPLIT), 256>>>(W1);
    gemm_kernel<1><<<dim3(16, KSPLIT), 256>>>(W2);
    gemv_loss_kernel<<<ROWS, 256>>>(W3, y, out, out_size);
}